// round 13
// baseline (speedup 1.0000x reference)
#include <cuda_runtime.h>
#include <cuda_bf16.h>

#define THR 1.2f

// ---------------------------------------------------------------------------
// Device globals
// ---------------------------------------------------------------------------
__device__ unsigned g_mask[512 * 1024 * 2];          // [t*64+b][px] uint2 channel masks
__device__ float    g_part[256 * 10];                // per-block FC partials
__device__ __nv_bfloat16 g_wsp[2 * 9 * 64 * 64];     // [pass][pos][cin][co] split w2
__device__ float    g_wfcT[65536 * 12];              // [co*1024+px][12] transposed wfc

__device__ __forceinline__ unsigned smem_u32(const void* p) {
    unsigned a;
    asm("{ .reg .u64 t; cvta.to.shared.u64 t, %1; cvt.u32.u64 %0, t; }"
        : "=r"(a) : "l"(p));
    return a;
}

#define LDMX4(r, addr) \
    asm volatile("ldmatrix.sync.aligned.m8n8.x4.shared.b16 {%0,%1,%2,%3}, [%4];" \
        : "=r"((r)[0]), "=r"((r)[1]), "=r"((r)[2]), "=r"((r)[3]) : "r"(addr))
#define LDMX4T(r, addr) \
    asm volatile("ldmatrix.sync.aligned.m8n8.x4.trans.shared.b16 {%0,%1,%2,%3}, [%4];" \
        : "=r"((r)[0]), "=r"((r)[1]), "=r"((r)[2]), "=r"((r)[3]) : "r"(addr))
#define MMA16816(c, a, bb0, bb1) \
    asm volatile("mma.sync.aligned.m16n8k16.row.col.f32.bf16.bf16.f32 " \
        "{%0,%1,%2,%3}, {%4,%5,%6,%7}, {%8,%9}, {%0,%1,%2,%3};" \
        : "+f"((c)[0]), "+f"((c)[1]), "+f"((c)[2]), "+f"((c)[3]) \
        : "r"((a)[0]), "r"((a)[1]), "r"((a)[2]), "r"((a)[3]), "r"(bb0), "r"(bb1))

// packed f32x2 helpers for k1
#define PACK2(d, x)   asm("mov.b64 %0, {%1,%1};" : "=l"(d) : "f"(x))
#define PACKAB(d, a, b) asm("mov.b64 %0, {%1,%2};" : "=l"(d) : "f"(a), "f"(b))
#define FMA2(acc, w, x2) \
    asm("fma.rn.f32x2 %0, %1, %2, %0;" : "+l"(acc) : "l"(w), "l"(x2))
#define UNPACK2(lo, hi, v) \
    asm("mov.b64 {%0,%1}, %2;" : "=f"(lo), "=f"(hi) : "l"(v))

// ---------------------------------------------------------------------------
// Kernel 1: conv1 (3->64) + LIF -> channel bitmasks (unchanged)
// ---------------------------------------------------------------------------
__global__ __launch_bounds__(256) void k1_conv1(const float* __restrict__ x,
                                                const float* __restrict__ w1,
                                                const float* __restrict__ b1) {
    __shared__ float xs[3 * 34 * 36];   // rows padded to 36 for vec4 loads
    __shared__ float ws[64 * 27];
    __shared__ float bs[64];

    const int tb  = blockIdx.x;
    const int tid = threadIdx.x;

    for (int i = tid; i < 64 * 27; i += 256) ws[i] = w1[i];
    if (tid < 64) bs[tid] = b1[tid];

    const float* xin = x + tb * 3 * 1024;
    for (int i = tid; i < 3 * 34 * 34; i += 256) {
        int cin = i / 1156, rem = i - cin * 1156;
        int yy = rem / 34, xx = rem - yy * 34;
        int gy = yy - 1, gx = xx - 1;
        float v = 0.f;
        if (gy >= 0 && gy < 32 && gx >= 0 && gx < 32)
            v = xin[cin * 1024 + gy * 32 + gx];
        xs[cin * 1224 + yy * 36 + xx] = v;
    }
    __syncthreads();

    const int wid  = tid >> 5;
    const int lane = tid & 31;          // channel pair: (lane, lane+32)

    unsigned long long wp[27];
#pragma unroll
    for (int k = 0; k < 27; k++)
        PACKAB(wp[k], ws[lane * 27 + k], ws[(lane + 32) * 27 + k]);
    unsigned long long bias2;
    PACKAB(bias2, bs[lane], bs[lane + 32]);

    for (int seg = wid; seg < 128; seg += 8) {
        const int y   = seg >> 2;
        const int xc0 = (seg & 3) * 8;

        unsigned long long acc2[8];
#pragma unroll
        for (int px = 0; px < 8; px++) acc2[px] = bias2;

#pragma unroll
        for (int cin = 0; cin < 3; cin++) {
            const float* base = xs + cin * 1224 + xc0;
#pragma unroll
            for (int dr = 0; dr < 3; dr++) {
                const float4* rp = (const float4*)(base + (y + dr) * 36);
                float4 f0 = rp[0], f1 = rp[1], f2 = rp[2];
                unsigned long long x2[10];
                PACK2(x2[0], f0.x); PACK2(x2[1], f0.y); PACK2(x2[2], f0.z); PACK2(x2[3], f0.w);
                PACK2(x2[4], f1.x); PACK2(x2[5], f1.y); PACK2(x2[6], f1.z); PACK2(x2[7], f1.w);
                PACK2(x2[8], f2.x); PACK2(x2[9], f2.y);
                const int wb = cin * 9 + dr * 3;
#pragma unroll
                for (int px = 0; px < 8; px++) {
                    FMA2(acc2[px], wp[wb],     x2[px]);
                    FMA2(acc2[px], wp[wb + 1], x2[px + 1]);
                    FMA2(acc2[px], wp[wb + 2], x2[px + 2]);
                }
            }
        }

#pragma unroll
        for (int px = 0; px < 8; px++) {
            float lo, hi;
            UNPACK2(lo, hi, acc2[px]);
            unsigned mlo = __ballot_sync(0xffffffffu, lo >= THR);
            unsigned mhi = __ballot_sync(0xffffffffu, hi >= THR);
            if (lane == 0)
                ((uint2*)g_mask)[tb * 1024 + seg * 8 + px] = make_uint2(mlo, mhi);
        }
    }
}

// ---------------------------------------------------------------------------
// Kernel 2a: split w2 -> bf16 hi+lo, layout [pass][pos][cin][co]
// ---------------------------------------------------------------------------
__global__ void k2a_split(const float* __restrict__ w2) {
    int i = blockIdx.x * 256 + threadIdx.x;
    if (i >= 36864) return;
    int co = i / 576, rest = i - co * 576;
    int cin = rest / 9, pos = rest - cin * 9;
    float w = w2[i];
    __nv_bfloat16 hi = __float2bfloat16(w);
    __nv_bfloat16 lo = __float2bfloat16(w - __bfloat162float(hi));
    int idx = pos * 4096 + cin * 64 + co;
    g_wsp[idx] = hi;
    g_wsp[36864 + idx] = lo;
}

// ---------------------------------------------------------------------------
// Kernel 2b: transpose wfc -> [co*1024+px][12]
// ---------------------------------------------------------------------------
__global__ void k2b_transpose(const float* __restrict__ wfc) {
    int i = blockIdx.x * 256 + threadIdx.x;   // 0..65535
    float v[10];
#pragma unroll
    for (int o = 0; o < 10; o++) v[o] = wfc[o * 65536 + i];
    float4* dst = (float4*)(g_wfcT + i * 12);
    dst[0] = make_float4(v[0], v[1], v[2], v[3]);
    dst[1] = make_float4(v[4], v[5], v[6], v[7]);
    dst[2] = make_float4(v[8], v[9], 0.f, 0.f);
}

// ---------------------------------------------------------------------------
// Kernel 2: conv2 via mma.sync bf16 (hi/lo) + LIF + count over t + FC.
// Grid: (2 strips of 16 rows, 64 b) = 128 CTAs, 256 threads = 8 warps.
// Warp = 2 rows = 4 m16 tiles. N split into two co-halves (32 co) so live
// accumulators are c[4][4][4] (64 regs) -> no spills. Mask LDGs for t+1 are
// issued before t's MMA loop (latency hidden); expansion stored after.
// SMEM: thr2 @0 (256B) | red @256 (320B) | LUT @1024 (4KB)
//       weights @5120 (147456B) | plane @152576: 612 rows x 128B (78336B)
// ---------------------------------------------------------------------------
#define OFF_RED   256
#define OFF_LUT   1024
#define OFF_B     5120
#define OFF_PLANE 152576
#define SMEM_K2   230912

__device__ __forceinline__ void expand_row(char* sm, int r, uint2 m) {
    char* pb = sm + OFF_PLANE + r * 128;
    const int rs = r & 7;
#pragma unroll
    for (int k = 0; k < 4; k++) {
        unsigned byte = (m.x >> (8 * k)) & 0xFFu;
        uint4 v = *(const uint4*)(sm + OFF_LUT + byte * 16);
        *(uint4*)(pb + ((k ^ rs) << 4)) = v;
    }
#pragma unroll
    for (int k = 4; k < 8; k++) {
        unsigned byte = (m.y >> (8 * (k - 4))) & 0xFFu;
        uint4 v = *(const uint4*)(sm + OFF_LUT + byte * 16);
        *(uint4*)(pb + ((k ^ rs) << 4)) = v;
    }
}

__device__ __forceinline__ uint2 load_mask(const uint2* gm, int t, int sy,
                                           int b, int r) {
    int iy = r / 34, ixp = r - iy * 34;
    int y = sy * 16 - 1 + iy;
    int ix = ixp - 1;
    uint2 m = make_uint2(0u, 0u);
    if ((unsigned)y < 32u && (unsigned)ix < 32u)
        m = __ldg(&gm[(t * 64 + b) * 1024 + y * 32 + ix]);
    return m;
}

__global__ __launch_bounds__(256, 1) void k2_mma(const float* __restrict__ b2) {
    extern __shared__ __align__(128) char sm[];
    const unsigned smb = smem_u32(sm);

    const int sy  = blockIdx.x;       // 16-row strip (0..1)
    const int b   = blockIdx.y;
    const int tid = threadIdx.x;
    const int wid = tid >> 5;
    const int lane = tid & 31;
    const int ry2 = wid * 2;          // first image row of this warp (0..14)

    // LUT: byte -> 8 bf16 (0/1)
    if (tid < 256) {
        int v = tid;
        unsigned w[4];
#pragma unroll
        for (int i = 0; i < 4; i++) {
            unsigned lo = ((v >> (2 * i)) & 1)     ? 0x3F80u : 0u;
            unsigned hi = ((v >> (2 * i + 1)) & 1) ? 0x3F800000u : 0u;
            w[i] = lo | hi;
        }
        *(uint4*)(sm + OFF_LUT + v * 16) = make_uint4(w[0], w[1], w[2], w[3]);
    }
    if (tid < 64) ((float*)sm)[tid] = THR - b2[tid];

    // weights -> SMEM with chunk swizzle j ^= (row&7)
    {
        const char* src = (const char*)g_wsp;
        for (int i = tid; i < 9216; i += 256) {
            int off = i * 16;
            int inner = off & 8191;
            int r = inner >> 7, j = (inner >> 4) & 7;
            uint4 v = *(const uint4*)(src + off);
            *(uint4*)(sm + OFF_B + (off & ~8191) + (r << 7) + ((j ^ (r & 7)) << 4)) = v;
        }
    }

    const uint2* gm = (const uint2*)g_mask;
    const unsigned p0 = smb + OFF_PLANE;
    const bool has3 = (tid < 100);    // rows: tid, tid+256, (tid+512 < 612)

    // prologue: load + expand t=0 masks
    uint2 m0 = load_mask(gm, 0, sy, b, tid);
    uint2 m1 = load_mask(gm, 0, sy, b, tid + 256);
    uint2 m2 = has3 ? load_mask(gm, 0, sy, b, tid + 512) : make_uint2(0u, 0u);
    __syncthreads();                  // LUT ready
    expand_row(sm, tid, m0);
    expand_row(sm, tid + 256, m1);
    if (has3) expand_row(sm, tid + 512, m2);
    __syncthreads();

    float thr2v[16];
#pragma unroll
    for (int nf = 0; nf < 8; nf++) {
        thr2v[nf * 2]     = ((const float*)sm)[nf * 8 + (lane & 3) * 2];
        thr2v[nf * 2 + 1] = ((const float*)sm)[nf * 8 + (lane & 3) * 2 + 1];
    }

    // nibble-packed spike counters: cntp[tile][q], nf in nibbles (cnt<=8)
    unsigned cntp[4][4];
#pragma unroll
    for (int h = 0; h < 4; h++)
#pragma unroll
        for (int q = 0; q < 4; q++) cntp[h][q] = 0u;

    for (int t = 0; t < 8; t++) {
        // issue next-t mask loads now; latency hides under the MMA loop
        if (t < 7) {
            m0 = load_mask(gm, t + 1, sy, b, tid);
            m1 = load_mask(gm, t + 1, sy, b, tid + 256);
            if (has3) m2 = load_mask(gm, t + 1, sy, b, tid + 512);
        }

#pragma unroll 1
        for (int coh = 0; coh < 2; coh++) {
            float c[4][4][4];   // [tile][nf-local][q]
#pragma unroll
            for (int h = 0; h < 4; h++)
#pragma unroll
                for (int l = 0; l < 4; l++)
#pragma unroll
                    for (int q = 0; q < 4; q++) c[h][l][q] = 0.f;

#pragma unroll 1
            for (int pos = 0; pos < 9; pos++) {
                const int dy = pos / 3, dx = pos - dy * 3;
                const int prbase = (ry2 + dy) * 34 + dx + (lane & 15);
                const unsigned wtb = smb + OFF_B + pos * 8192;
#pragma unroll 1
                for (int kt = 0; kt < 4; kt++) {
                    const unsigned kcol = (unsigned)(kt * 2 + (lane >> 4));
                    unsigned a[4][4];
#pragma unroll
                    for (int h = 0; h < 4; h++) {
                        const int prb = prbase + (h >> 1) * 34 + (h & 1) * 16;
                        LDMX4(a[h], p0 + prb * 128 + ((kcol ^ (prb & 7)) << 4));
                    }
                    const int brow = kt * 16 + (lane & 15);
                    const unsigned bjb = (unsigned)(lane >> 4);
                    const unsigned bbase = brow * 128;
#pragma unroll
                    for (int pass = 0; pass < 2; pass++) {
                        const unsigned wb = wtb + pass * 73728 + bbase;
#pragma unroll
                        for (int nt = 0; nt < 2; nt++) {
                            const unsigned chunk = coh * 4 + nt * 2 + bjb;
                            unsigned bb[4];
                            LDMX4T(bb, wb + ((chunk ^ (brow & 7)) << 4));
#pragma unroll
                            for (int h = 0; h < 4; h++) {
                                MMA16816(c[h][nt * 2],     a[h], bb[0], bb[1]);
                                MMA16816(c[h][nt * 2 + 1], a[h], bb[2], bb[3]);
                            }
                        }
                    }
                }
            }

            // threshold this co-half -> nibble-packed counts
#pragma unroll
            for (int h = 0; h < 4; h++)
#pragma unroll
                for (int l = 0; l < 4; l++) {
                    const int nf = coh * 4 + l;
#pragma unroll
                    for (int q = 0; q < 4; q++)
                        cntp[h][q] += (c[h][l][q] >= thr2v[nf * 2 + (q & 1)])
                                          ? (1u << (4 * nf)) : 0u;
                }
        }

        __syncthreads();   // all plane reads for t done
        if (t < 7) {
            expand_row(sm, tid, m0);
            expand_row(sm, tid + 256, m1);
            if (has3) expand_row(sm, tid + 512, m2);
            __syncthreads();
        }
    }

    // --- fused FC fold
    float oa[10];
#pragma unroll
    for (int o = 0; o < 10; o++) oa[o] = 0.f;
#pragma unroll
    for (int h = 0; h < 4; h++) {
        const int gpbase = (sy * 16 + ry2 + (h >> 1)) * 32 + (h & 1) * 16;
#pragma unroll
        for (int q = 0; q < 4; q++) {
            const int gp = gpbase + (lane >> 2) + ((q >> 1) << 3);
#pragma unroll
            for (int nf = 0; nf < 8; nf++) {
                const int co = nf * 8 + (lane & 3) * 2 + (q & 1);
                const float4* p = (const float4*)(g_wfcT + (co * 1024 + gp) * 12);
                float4 f0 = p[0], f1 = p[1], f2 = p[2];
                const float cc = (float)((cntp[h][q] >> (4 * nf)) & 0xFu);
                oa[0] += cc * f0.x; oa[1] += cc * f0.y; oa[2] += cc * f0.z; oa[3] += cc * f0.w;
                oa[4] += cc * f1.x; oa[5] += cc * f1.y; oa[6] += cc * f1.z; oa[7] += cc * f1.w;
                oa[8] += cc * f2.x; oa[9] += cc * f2.y;
            }
        }
    }

    float* red = (float*)(sm + OFF_RED);
#pragma unroll
    for (int o = 0; o < 10; o++) {
        float v = oa[o];
        v += __shfl_down_sync(0xffffffffu, v, 16);
        v += __shfl_down_sync(0xffffffffu, v, 8);
        v += __shfl_down_sync(0xffffffffu, v, 4);
        v += __shfl_down_sync(0xffffffffu, v, 2);
        v += __shfl_down_sync(0xffffffffu, v, 1);
        if (lane == 0) red[wid * 10 + o] = v;
    }
    __syncthreads();
    if (tid < 10) {
        float s = 0.f;
#pragma unroll
        for (int w = 0; w < 8; w++) s += red[w * 10 + tid];
        g_part[(b * 2 + sy) * 10 + tid] = s;
    }
}

// ---------------------------------------------------------------------------
// Kernel 3: final reduction
// ---------------------------------------------------------------------------
__global__ void k3_final(const float* __restrict__ bfc, float* __restrict__ out) {
    const int tid = threadIdx.x;
    if (tid < 640) {
        const int b = tid / 10, o = tid - b * 10;
        float s = 8.f * bfc[o];
#pragma unroll
        for (int k = 0; k < 2; k++) s += g_part[(b * 2 + k) * 10 + o];
        out[tid] = s;
    }
}

extern "C" void kernel_launch(void* const* d_in, const int* in_sizes, int n_in,
                              void* d_out, int out_size) {
    const float* x   = (const float*)d_in[0];  // [8,64,3,32,32]
    const float* w1  = (const float*)d_in[1];  // [64,3,3,3]
    const float* b1  = (const float*)d_in[2];  // [64]
    const float* w2  = (const float*)d_in[3];  // [64,64,3,3]
    const float* b2  = (const float*)d_in[4];  // [64]
    const float* wfc = (const float*)d_in[5];  // [10, 65536]
    const float* bfc = (const float*)d_in[6];  // [10]
    float* out = (float*)d_out;                // [64,10]

    cudaFuncSetAttribute(k2_mma, cudaFuncAttributeMaxDynamicSharedMemorySize,
                         SMEM_K2);

    k1_conv1<<<512, 256>>>(x, w1, b1);
    k2a_split<<<144, 256>>>(w2);
    k2b_transpose<<<256, 256>>>(wfc);
    k2_mma<<<dim3(2, 64), 256, SMEM_K2>>>(b2);
    k3_final<<<1, 640>>>(bfc, out);
}

// round 14
// speedup vs baseline: 1.4221x; 1.4221x over previous
#include <cuda_runtime.h>
#include <cuda_bf16.h>

#define THR 1.2f

// ---------------------------------------------------------------------------
// Device globals
// ---------------------------------------------------------------------------
__device__ unsigned g_mask[512 * 1024 * 2];          // [t*64+b][px] uint2 channel masks
__device__ float    g_part[256 * 10];                // per-block FC partials
__device__ __nv_bfloat16 g_wsp[2 * 9 * 64 * 64];     // [pass][pos][cin][co] split w2
__device__ float    g_wfcT[65536 * 12];              // [co*1024+px][12] transposed wfc

__device__ __forceinline__ unsigned smem_u32(const void* p) {
    unsigned a;
    asm("{ .reg .u64 t; cvta.to.shared.u64 t, %1; cvt.u32.u64 %0, t; }"
        : "=r"(a) : "l"(p));
    return a;
}

#define LDMX4(r, addr) \
    asm volatile("ldmatrix.sync.aligned.m8n8.x4.shared.b16 {%0,%1,%2,%3}, [%4];" \
        : "=r"((r)[0]), "=r"((r)[1]), "=r"((r)[2]), "=r"((r)[3]) : "r"(addr))
#define LDMX4T(r, addr) \
    asm volatile("ldmatrix.sync.aligned.m8n8.x4.trans.shared.b16 {%0,%1,%2,%3}, [%4];" \
        : "=r"((r)[0]), "=r"((r)[1]), "=r"((r)[2]), "=r"((r)[3]) : "r"(addr))
#define MMA16816(c, a, bb0, bb1) \
    asm volatile("mma.sync.aligned.m16n8k16.row.col.f32.bf16.bf16.f32 " \
        "{%0,%1,%2,%3}, {%4,%5,%6,%7}, {%8,%9}, {%0,%1,%2,%3};" \
        : "+f"((c)[0]), "+f"((c)[1]), "+f"((c)[2]), "+f"((c)[3]) \
        : "r"((a)[0]), "r"((a)[1]), "r"((a)[2]), "r"((a)[3]), "r"(bb0), "r"(bb1))

// packed f32x2 helpers for k1
#define PACK2(d, x)   asm("mov.b64 %0, {%1,%1};" : "=l"(d) : "f"(x))
#define PACKAB(d, a, b) asm("mov.b64 %0, {%1,%2};" : "=l"(d) : "f"(a), "f"(b))
#define FMA2(acc, w, x2) \
    asm("fma.rn.f32x2 %0, %1, %2, %0;" : "+l"(acc) : "l"(w), "l"(x2))
#define UNPACK2(lo, hi, v) \
    asm("mov.b64 {%0,%1}, %2;" : "=f"(lo), "=f"(hi) : "l"(v))

// ---------------------------------------------------------------------------
// Kernel 1: conv1 (3->64) + LIF -> channel bitmasks (unchanged)
// ---------------------------------------------------------------------------
__global__ __launch_bounds__(256) void k1_conv1(const float* __restrict__ x,
                                                const float* __restrict__ w1,
                                                const float* __restrict__ b1) {
    __shared__ float xs[3 * 34 * 36];   // rows padded to 36 for vec4 loads
    __shared__ float ws[64 * 27];
    __shared__ float bs[64];

    const int tb  = blockIdx.x;
    const int tid = threadIdx.x;

    for (int i = tid; i < 64 * 27; i += 256) ws[i] = w1[i];
    if (tid < 64) bs[tid] = b1[tid];

    const float* xin = x + tb * 3 * 1024;
    for (int i = tid; i < 3 * 34 * 34; i += 256) {
        int cin = i / 1156, rem = i - cin * 1156;
        int yy = rem / 34, xx = rem - yy * 34;
        int gy = yy - 1, gx = xx - 1;
        float v = 0.f;
        if (gy >= 0 && gy < 32 && gx >= 0 && gx < 32)
            v = xin[cin * 1024 + gy * 32 + gx];
        xs[cin * 1224 + yy * 36 + xx] = v;
    }
    __syncthreads();

    const int wid  = tid >> 5;
    const int lane = tid & 31;          // channel pair: (lane, lane+32)

    unsigned long long wp[27];
#pragma unroll
    for (int k = 0; k < 27; k++)
        PACKAB(wp[k], ws[lane * 27 + k], ws[(lane + 32) * 27 + k]);
    unsigned long long bias2;
    PACKAB(bias2, bs[lane], bs[lane + 32]);

    for (int seg = wid; seg < 128; seg += 8) {
        const int y   = seg >> 2;
        const int xc0 = (seg & 3) * 8;

        unsigned long long acc2[8];
#pragma unroll
        for (int px = 0; px < 8; px++) acc2[px] = bias2;

#pragma unroll
        for (int cin = 0; cin < 3; cin++) {
            const float* base = xs + cin * 1224 + xc0;
#pragma unroll
            for (int dr = 0; dr < 3; dr++) {
                const float4* rp = (const float4*)(base + (y + dr) * 36);
                float4 f0 = rp[0], f1 = rp[1], f2 = rp[2];
                unsigned long long x2[10];
                PACK2(x2[0], f0.x); PACK2(x2[1], f0.y); PACK2(x2[2], f0.z); PACK2(x2[3], f0.w);
                PACK2(x2[4], f1.x); PACK2(x2[5], f1.y); PACK2(x2[6], f1.z); PACK2(x2[7], f1.w);
                PACK2(x2[8], f2.x); PACK2(x2[9], f2.y);
                const int wb = cin * 9 + dr * 3;
#pragma unroll
                for (int px = 0; px < 8; px++) {
                    FMA2(acc2[px], wp[wb],     x2[px]);
                    FMA2(acc2[px], wp[wb + 1], x2[px + 1]);
                    FMA2(acc2[px], wp[wb + 2], x2[px + 2]);
                }
            }
        }

#pragma unroll
        for (int px = 0; px < 8; px++) {
            float lo, hi;
            UNPACK2(lo, hi, acc2[px]);
            unsigned mlo = __ballot_sync(0xffffffffu, lo >= THR);
            unsigned mhi = __ballot_sync(0xffffffffu, hi >= THR);
            if (lane == 0)
                ((uint2*)g_mask)[tb * 1024 + seg * 8 + px] = make_uint2(mlo, mhi);
        }
    }
}

// ---------------------------------------------------------------------------
// Kernel 2a: split w2 -> bf16 hi+lo, layout [pass][pos][cin][co]
// ---------------------------------------------------------------------------
__global__ void k2a_split(const float* __restrict__ w2) {
    int i = blockIdx.x * 256 + threadIdx.x;
    if (i >= 36864) return;
    int co = i / 576, rest = i - co * 576;
    int cin = rest / 9, pos = rest - cin * 9;
    float w = w2[i];
    __nv_bfloat16 hi = __float2bfloat16(w);
    __nv_bfloat16 lo = __float2bfloat16(w - __bfloat162float(hi));
    int idx = pos * 4096 + cin * 64 + co;
    g_wsp[idx] = hi;
    g_wsp[36864 + idx] = lo;
}

// ---------------------------------------------------------------------------
// Kernel 2b: transpose wfc -> [co*1024+px][12]
// ---------------------------------------------------------------------------
__global__ void k2b_transpose(const float* __restrict__ wfc) {
    int i = blockIdx.x * 256 + threadIdx.x;   // 0..65535
    float v[10];
#pragma unroll
    for (int o = 0; o < 10; o++) v[o] = wfc[o * 65536 + i];
    float4* dst = (float4*)(g_wfcT + i * 12);
    dst[0] = make_float4(v[0], v[1], v[2], v[3]);
    dst[1] = make_float4(v[4], v[5], v[6], v[7]);
    dst[2] = make_float4(v[8], v[9], 0.f, 0.f);
}

// ---------------------------------------------------------------------------
// Kernel 2: conv2 via mma.sync bf16 (hi/lo) + LIF + count over t + FC.
// Grid: (2 strips, 64 b, 2 co-halves) = 256 CTAs, 256 threads = 8 warps.
// Warp = 2 rows = 4 m16 tiles; CTA owns 32 output channels -> c[4][4][4]
// (64 accum regs, no spills). B tables are 64B rows, swizzle j^((row>>1)&3).
// SMEM: thr2 @0 (256B) | red @256 (320B) | LUT @1024 (4KB)
//       weights @5120: 2x9x64 rows x 64B (73728B)
//       plane @78848: 612 rows x 128B (78336B)  -> total 157184
// ---------------------------------------------------------------------------
#define OFF_RED   256
#define OFF_LUT   1024
#define OFF_B     5120
#define OFF_PLANE 78848
#define SMEM_K2   157184

__global__ __launch_bounds__(256, 1) void k2_mma(const float* __restrict__ b2) {
    extern __shared__ __align__(128) char sm[];
    const unsigned smb = smem_u32(sm);

    const int sy  = blockIdx.x;       // 16-row strip (0..1)
    const int b   = blockIdx.y;
    const int zc  = blockIdx.z;       // co-half: channels [zc*32, zc*32+32)
    const int tid = threadIdx.x;
    const int wid = tid >> 5;
    const int lane = tid & 31;
    const int ry2 = wid * 2;          // first image row of this warp (0..14)

    // LUT: byte -> 8 bf16 (0/1)
    if (tid < 256) {
        int v = tid;
        unsigned w[4];
#pragma unroll
        for (int i = 0; i < 4; i++) {
            unsigned lo = ((v >> (2 * i)) & 1)     ? 0x3F80u : 0u;
            unsigned hi = ((v >> (2 * i + 1)) & 1) ? 0x3F800000u : 0u;
            w[i] = lo | hi;
        }
        *(uint4*)(sm + OFF_LUT + v * 16) = make_uint4(w[0], w[1], w[2], w[3]);
    }
    if (tid < 64) ((float*)sm)[tid] = THR - b2[tid];

    // this CTA's co-half of the weights -> SMEM, 64B rows, swizzle j^((cin>>1)&3)
    {
        const char* src = (const char*)g_wsp;
        for (int ci = tid; ci < 4608; ci += 256) {
            int row = ci >> 2;                 // (pass*9+pos)*64 + cin
            int j   = ci & 3;
            int cin = row & 63;
            uint4 v = *(const uint4*)(src + row * 128 + zc * 64 + j * 16);
            *(uint4*)(sm + OFF_B + row * 64 + ((j ^ ((cin >> 1) & 3)) << 4)) = v;
        }
    }
    __syncthreads();

    float thr2v[8];    // [l][q-parity], co = zc*32 + l*8 + (lane&3)*2 + parity
#pragma unroll
    for (int l = 0; l < 4; l++) {
        thr2v[l * 2]     = ((const float*)sm)[zc * 32 + l * 8 + (lane & 3) * 2];
        thr2v[l * 2 + 1] = ((const float*)sm)[zc * 32 + l * 8 + (lane & 3) * 2 + 1];
    }

    // nibble-packed spike counters: cntp[tile][q], l in nibbles (cnt<=8)
    unsigned cntp[4][4];
#pragma unroll
    for (int h = 0; h < 4; h++)
#pragma unroll
        for (int q = 0; q < 4; q++) cntp[h][q] = 0u;

    const uint2* gm = (const uint2*)g_mask;
    const unsigned p0 = smb + OFF_PLANE;

    for (int t = 0; t < 8; t++) {
        // --- expand spike masks for this t: 612 rows (18 image rows + x halo)
        for (int r = tid; r < 612; r += 256) {
            int iy = r / 34, ixp = r - iy * 34;
            int y = sy * 16 - 1 + iy;
            int ix = ixp - 1;
            uint2 m = make_uint2(0u, 0u);
            if ((unsigned)y < 32u && (unsigned)ix < 32u)
                m = gm[(t * 64 + b) * 1024 + y * 32 + ix];
            char* pb = sm + OFF_PLANE + r * 128;
            const int rs = r & 7;
#pragma unroll
            for (int k = 0; k < 4; k++) {
                unsigned byte = (m.x >> (8 * k)) & 0xFFu;
                uint4 v = *(const uint4*)(sm + OFF_LUT + byte * 16);
                *(uint4*)(pb + ((k ^ rs) << 4)) = v;
            }
#pragma unroll
            for (int k = 4; k < 8; k++) {
                unsigned byte = (m.y >> (8 * (k - 4))) & 0xFFu;
                uint4 v = *(const uint4*)(sm + OFF_LUT + byte * 16);
                *(uint4*)(pb + ((k ^ rs) << 4)) = v;
            }
        }
        __syncthreads();

        float c[4][4][4];   // [tile][l][q] fp32 accumulators (hi+lo summed)
#pragma unroll
        for (int h = 0; h < 4; h++)
#pragma unroll
            for (int l = 0; l < 4; l++)
#pragma unroll
                for (int q = 0; q < 4; q++) c[h][l][q] = 0.f;

#pragma unroll 1
        for (int pos = 0; pos < 9; pos++) {
            const int dy = pos / 3, dx = pos - dy * 3;
            const int prbase = (ry2 + dy) * 34 + dx + (lane & 15);
#pragma unroll 1
            for (int kt = 0; kt < 4; kt++) {
                const unsigned kcol = (unsigned)(kt * 2 + (lane >> 4));
                unsigned a[4][4];
#pragma unroll
                for (int h = 0; h < 4; h++) {
                    const int prb = prbase + (h >> 1) * 34 + (h & 1) * 16;
                    LDMX4(a[h], p0 + prb * 128 + ((kcol ^ (prb & 7)) << 4));
                }
                const int brow = kt * 16 + (lane & 15);
                const unsigned bjb = (unsigned)(lane >> 4);
                const unsigned bsw = (unsigned)((brow >> 1) & 3);
                const unsigned bbase = brow * 64;
#pragma unroll
                for (int pass = 0; pass < 2; pass++) {
                    const unsigned wb = smb + OFF_B + (pass * 9 + pos) * 4096 + bbase;
#pragma unroll
                    for (int nt = 0; nt < 2; nt++) {
                        unsigned bb[4];
                        LDMX4T(bb, wb + (((nt * 2 + bjb) ^ bsw) << 4));
#pragma unroll
                        for (int h = 0; h < 4; h++) {
                            MMA16816(c[h][nt * 2],     a[h], bb[0], bb[1]);
                            MMA16816(c[h][nt * 2 + 1], a[h], bb[2], bb[3]);
                        }
                    }
                }
            }
        }

        // threshold -> nibble-packed spike counts
#pragma unroll
        for (int h = 0; h < 4; h++)
#pragma unroll
            for (int l = 0; l < 4; l++)
#pragma unroll
                for (int q = 0; q < 4; q++)
                    cntp[h][q] += (c[h][l][q] >= thr2v[l * 2 + (q & 1)])
                                      ? (1u << (4 * l)) : 0u;

        __syncthreads();   // MMA reads done before next t overwrites plane
    }

    // --- fused FC fold (this CTA's 32 channels only)
    float oa[10];
#pragma unroll
    for (int o = 0; o < 10; o++) oa[o] = 0.f;
#pragma unroll
    for (int h = 0; h < 4; h++) {
        const int gpbase = (sy * 16 + ry2 + (h >> 1)) * 32 + (h & 1) * 16;
#pragma unroll
        for (int q = 0; q < 4; q++) {
            const int gp = gpbase + (lane >> 2) + ((q >> 1) << 3);
#pragma unroll
            for (int l = 0; l < 4; l++) {
                const int co = zc * 32 + l * 8 + (lane & 3) * 2 + (q & 1);
                const float4* p = (const float4*)(g_wfcT + (co * 1024 + gp) * 12);
                float4 f0 = p[0], f1 = p[1], f2 = p[2];
                const float cc = (float)((cntp[h][q] >> (4 * l)) & 0xFu);
                oa[0] += cc * f0.x; oa[1] += cc * f0.y; oa[2] += cc * f0.z; oa[3] += cc * f0.w;
                oa[4] += cc * f1.x; oa[5] += cc * f1.y; oa[6] += cc * f1.z; oa[7] += cc * f1.w;
                oa[8] += cc * f2.x; oa[9] += cc * f2.y;
            }
        }
    }

    float* red = (float*)(sm + OFF_RED);
#pragma unroll
    for (int o = 0; o < 10; o++) {
        float v = oa[o];
        v += __shfl_down_sync(0xffffffffu, v, 16);
        v += __shfl_down_sync(0xffffffffu, v, 8);
        v += __shfl_down_sync(0xffffffffu, v, 4);
        v += __shfl_down_sync(0xffffffffu, v, 2);
        v += __shfl_down_sync(0xffffffffu, v, 1);
        if (lane == 0) red[wid * 10 + o] = v;
    }
    __syncthreads();
    if (tid < 10) {
        float s = 0.f;
#pragma unroll
        for (int w = 0; w < 8; w++) s += red[w * 10 + tid];
        g_part[((b * 2 + sy) * 2 + zc) * 10 + tid] = s;
    }
}

// ---------------------------------------------------------------------------
// Kernel 3: final reduction
// ---------------------------------------------------------------------------
__global__ void k3_final(const float* __restrict__ bfc, float* __restrict__ out) {
    const int tid = threadIdx.x;
    if (tid < 640) {
        const int b = tid / 10, o = tid - b * 10;
        float s = 8.f * bfc[o];
#pragma unroll
        for (int k = 0; k < 4; k++) s += g_part[(b * 4 + k) * 10 + o];
        out[tid] = s;
    }
}

extern "C" void kernel_launch(void* const* d_in, const int* in_sizes, int n_in,
                              void* d_out, int out_size) {
    const float* x   = (const float*)d_in[0];  // [8,64,3,32,32]
    const float* w1  = (const float*)d_in[1];  // [64,3,3,3]
    const float* b1  = (const float*)d_in[2];  // [64]
    const float* w2  = (const float*)d_in[3];  // [64,64,3,3]
    const float* b2  = (const float*)d_in[4];  // [64]
    const float* wfc = (const float*)d_in[5];  // [10, 65536]
    const float* bfc = (const float*)d_in[6];  // [10]
    float* out = (float*)d_out;                // [64,10]

    cudaFuncSetAttribute(k2_mma, cudaFuncAttributeMaxDynamicSharedMemorySize,
                         SMEM_K2);

    k1_conv1<<<512, 256>>>(x, w1, b1);
    k2a_split<<<144, 256>>>(w2);
    k2b_transpose<<<256, 256>>>(wfc);
    k2_mma<<<dim3(2, 64, 2), 256, SMEM_K2>>>(b2);
    k3_final<<<1, 640>>>(bfc, out);
}